// round 9
// baseline (speedup 1.0000x reference)
#include <cuda_runtime.h>
#include <cuda_bf16.h>
#include <math.h>
#include <stdint.h>

#define NROWS 16384      // B*L
#define DIN   1024       // input dim
#define MLAT  8192       // latent dim
#define KSEL  64         // top-k
#define WINCAP 64        // max ambiguous candidates per row
#define DELTA 1e-4f      // ambiguity window (>> bf16-split GEMM noise ~5e-6)
#define KC    504        // Eigen gebp kc (VALIDATED round 5 — do not change)
#define CANDCAP 256      // in-bin candidate cap for fast threshold path

// ---------------- scratch (static __device__ — allocation-free) ----------------
__device__ float g_Wt[(size_t)MLAT * DIN];
__device__ int   g_topk_idx[(size_t)NROWS * KSEL];
__device__ float g_topk_val[(size_t)NROWS * KSEL];
__device__ __align__(16) __nv_bfloat16 g_x_hi[(size_t)NROWS * DIN];
__device__ __align__(16) __nv_bfloat16 g_x_lo[(size_t)NROWS * DIN];
__device__ __align__(16) __nv_bfloat16 g_w_hi[(size_t)MLAT * DIN];
__device__ __align__(16) __nv_bfloat16 g_w_lo[(size_t)MLAT * DIN];

// ---------------- PTX helpers (baseline ISA only — no 'a' features) ----------------
__device__ __forceinline__ uint32_t smem_u32(const void* p) {
    uint32_t a;
    asm("{ .reg .u64 t; cvta.to.shared.u64 t, %1; cvt.u32.u64 %0, t; }" : "=r"(a) : "l"(p));
    return a;
}
__device__ __forceinline__ void cp_async16(uint32_t s, const void* g) {
    asm volatile("cp.async.cg.shared.global [%0], [%1], 16;" :: "r"(s), "l"(g));
}
#define CP_COMMIT() asm volatile("cp.async.commit_group;" ::: "memory")
#define CP_WAIT(n)  asm volatile("cp.async.wait_group %0;" :: "n"(n) : "memory")

__device__ __forceinline__ void ldsm_x4(uint32_t* r, uint32_t addr) {
    asm volatile("ldmatrix.sync.aligned.m8n8.x4.shared.b16 {%0,%1,%2,%3}, [%4];"
        : "=r"(r[0]), "=r"(r[1]), "=r"(r[2]), "=r"(r[3]) : "r"(addr));
}
__device__ __forceinline__ void mma_bf16(float* d, const uint32_t* a, const uint32_t* b) {
    asm volatile("mma.sync.aligned.m16n8k16.row.col.f32.bf16.bf16.f32 "
        "{%0,%1,%2,%3}, {%4,%5,%6,%7}, {%8,%9}, {%0,%1,%2,%3};"
        : "+f"(d[0]), "+f"(d[1]), "+f"(d[2]), "+f"(d[3])
        : "r"(a[0]), "r"(a[1]), "r"(a[2]), "r"(a[3]), "r"(b[0]), "r"(b[1]));
}

// ---------------- kernel 0: fp32 -> bf16 hi/lo split ----------------
__global__ void split_kernel(const float* __restrict__ in,
                             __nv_bfloat16* __restrict__ hi,
                             __nv_bfloat16* __restrict__ lo, int n4) {
    const int i = blockIdx.x * blockDim.x + threadIdx.x;
    if (i >= n4) return;
    const float4 f = ((const float4*)in)[i];
    __nv_bfloat16 h0 = __float2bfloat16(f.x), h1 = __float2bfloat16(f.y);
    __nv_bfloat16 h2 = __float2bfloat16(f.z), h3 = __float2bfloat16(f.w);
    __nv_bfloat16 l0 = __float2bfloat16(f.x - __bfloat162float(h0));
    __nv_bfloat16 l1 = __float2bfloat16(f.y - __bfloat162float(h1));
    __nv_bfloat16 l2 = __float2bfloat16(f.z - __bfloat162float(h2));
    __nv_bfloat16 l3 = __float2bfloat16(f.w - __bfloat162float(h3));
    ushort4 H, L;
    H.x = __bfloat16_as_ushort(h0); H.y = __bfloat16_as_ushort(h1);
    H.z = __bfloat16_as_ushort(h2); H.w = __bfloat16_as_ushort(h3);
    L.x = __bfloat16_as_ushort(l0); L.y = __bfloat16_as_ushort(l1);
    L.z = __bfloat16_as_ushort(l2); L.w = __bfloat16_as_ushort(l3);
    ((ushort4*)hi)[i] = H;
    ((ushort4*)lo)[i] = L;
}

// ---------------- kernel 1+2 fused: W = prev + alpha*(dec-prev), write W and W^T ----------------
__global__ void compute_WT_kernel(const float* __restrict__ dec_w,
                                  const float* __restrict__ prev_w,
                                  const float* __restrict__ s_ptr,
                                  const int*   __restrict__ task_ptr,
                                  float* __restrict__ W_out) {
    __shared__ float tile[32][33];
    const int m0 = blockIdx.x * 32;   // latent dim
    const int d0 = blockIdx.y * 32;   // input dim
    const int tx = threadIdx.x, ty = threadIdx.y;
    const float s = *s_ptr;
    const int task = *task_ptr;
    const float sig = 1.0f / (1.0f + expf(-s));
    const float alpha = (task == 0) ? 1.0f : (1.0f / (float)(task + 1)) * sig;
#pragma unroll
    for (int j = 0; j < 32; j += 8) {
        const size_t idx = (size_t)(d0 + ty + j) * MLAT + m0 + tx;
        const float p = prev_w[idx];
        const float d = dec_w[idx];
        const float w = p + alpha * (d - p);   // match ref rounding: mul then add
        W_out[idx] = w;
        tile[ty + j][tx] = w;
    }
    __syncthreads();
#pragma unroll
    for (int j = 0; j < 32; j += 8)
        g_Wt[(size_t)(m0 + ty + j) * DIN + d0 + tx] = tile[tx][ty + j];
}

// ---------------- kernel 3: HMMA bf16-2split encoder GEMM (round-7 loop ordering) ----------------
#define ROWB   80
#define TILE_B (128 * ROWB)
#define STAGE_BYTES (4 * TILE_B)
#define A_HI_OFF 0
#define A_LO_OFF TILE_B
#define B_HI_OFF (2 * TILE_B)
#define B_LO_OFF (3 * TILE_B)
#define SMEM_GEMM (2 * STAGE_BYTES)     // 81920 B

__global__ __launch_bounds__(256, 2)
void enc_gemm_mma(float* __restrict__ C, const float* __restrict__ bias) {
    extern __shared__ char smem[];
    const uint32_t sb = smem_u32(smem);
    const int tid = threadIdx.x;
    const int wid = tid >> 5, lid = tid & 31;
    const int m0 = blockIdx.y * 128, n0 = blockIdx.x * 128;
    const int warpM = wid >> 2, warpN = wid & 3;

    auto load_chunk = [&](int kt, int st) {
        const uint32_t base = sb + st * STAGE_BYTES;
#pragma unroll
        for (int t = 0; t < 2; ++t) {
            const int c = t * 256 + tid;          // 0..511
            const int row = c >> 2, q = c & 3;
            const size_t gA = (size_t)(m0 + row) * DIN + kt * 32 + q * 8;
            const size_t gB = (size_t)(n0 + row) * DIN + kt * 32 + q * 8;
            const uint32_t so = row * ROWB + q * 16;
            cp_async16(base + A_HI_OFF + so, g_x_hi + gA);
            cp_async16(base + A_LO_OFF + so, g_x_lo + gA);
            cp_async16(base + B_HI_OFF + so, g_w_hi + gB);
            cp_async16(base + B_LO_OFF + so, g_w_lo + gB);
        }
        CP_COMMIT();
    };

    float acc[4][4][4] = {};
    load_chunk(0, 0);

    for (int kt = 0; kt < 32; ++kt) {
        const int st = kt & 1;
        // round-7 ordering: issue next-stage loads BEFORE waiting — LDGSTS issue
        // overlaps the wait-stall, and prefetch has full compute span to land.
        if (kt < 31) { load_chunk(kt + 1, st ^ 1); CP_WAIT(1); }
        else         { CP_WAIT(0); }
        __syncthreads();

        const uint32_t base = sb + st * STAGE_BYTES;
        const int arow = (lid & 8) + (lid & 7);
        const int brow = ((lid & 16) ? 8 : 0) + (lid & 7);
#pragma unroll
        for (int ks = 0; ks < 2; ++ks) {
            const int koff = ks * 32;
            const int akb = koff + ((lid & 16) ? 16 : 0);
            const int bkb = koff + ((lid & 8) ? 16 : 0);
            uint32_t Ah[4][4], Al[4][4], Bh[2][4], Bl[2][4];
#pragma unroll
            for (int mt = 0; mt < 4; ++mt) {
                const uint32_t r = (uint32_t)(warpM * 64 + mt * 16 + arow) * ROWB + akb;
                ldsm_x4(Ah[mt], base + A_HI_OFF + r);
                ldsm_x4(Al[mt], base + A_LO_OFF + r);
            }
#pragma unroll
            for (int ng = 0; ng < 2; ++ng) {
                const uint32_t r = (uint32_t)(warpN * 32 + ng * 16 + brow) * ROWB + bkb;
                ldsm_x4(Bh[ng], base + B_HI_OFF + r);
                ldsm_x4(Bl[ng], base + B_LO_OFF + r);
            }
#pragma unroll
            for (int mt = 0; mt < 4; ++mt)
#pragma unroll
                for (int ng = 0; ng < 2; ++ng)
#pragma unroll
                    for (int sub = 0; sub < 2; ++sub) {
                        float* d = acc[mt][ng * 2 + sub];
                        mma_bf16(d, Ah[mt], &Bh[ng][sub * 2]);
                        mma_bf16(d, Ah[mt], &Bl[ng][sub * 2]);
                        mma_bf16(d, Al[mt], &Bh[ng][sub * 2]);
                    }
        }
        __syncthreads();
    }

    // epilogue
    const int rbase = m0 + warpM * 64 + (lid >> 2);
    const int cbase = n0 + warpN * 32 + (lid & 3) * 2;
#pragma unroll
    for (int nt = 0; nt < 4; ++nt) {
        const int col = cbase + nt * 8;
        const float b0 = bias[col], b1 = bias[col + 1];
#pragma unroll
        for (int mt = 0; mt < 4; ++mt) {
            float* p0 = C + (size_t)(rbase + mt * 16) * MLAT + col;
            float2 v0, v1;
            v0.x = acc[mt][nt][0] + b0; v0.y = acc[mt][nt][1] + b1;
            v1.x = acc[mt][nt][2] + b0; v1.y = acc[mt][nt][3] + b1;
            *(float2*)p0 = v0;
            *(float2*)(p0 + 8 * MLAT) = v1;
        }
    }
}

// ---------------- kernel 4: per-row top-64, histogram threshold + Eigen kc=504 arbitration ----------------
__global__ __launch_bounds__(256)
void topk_kernel(const float* __restrict__ latent,
                 const float* __restrict__ x,
                 const float* __restrict__ enc_w,
                 const float* __restrict__ enc_b) {
    const int row = blockIdx.x;
    const int tid = threadIdx.x;
    const float* lrow = latent + (size_t)row * MLAT;

    __shared__ uint32_t hist[4096];     // 12-bit key = u >> 19
    __shared__ int s_part[256];
    __shared__ int s_binb, s_above, s_nc;
    __shared__ unsigned s_cand[CANDCAP];
    __shared__ int s_red[8];
    __shared__ int s_total;

#pragma unroll
    for (int i = 0; i < 16; ++i) hist[tid + i * 256] = 0;

    unsigned u[32];
    unsigned smask = 0;
#pragma unroll
    for (int i = 0; i < 32; ++i) {
        const float f = lrow[i * 256 + tid];
        const unsigned fb = __float_as_uint(f);
        u[i] = fb & 0x7FFFFFFFu;
        smask |= (fb >> 31) << i;
    }
    __syncthreads();
#pragma unroll
    for (int i = 0; i < 32; ++i) atomicAdd(&hist[u[i] >> 19], 1u);
    __syncthreads();

    // suffix scan to find bin of the 64th-largest
    {
        int p = 0;
#pragma unroll
        for (int j = 0; j < 16; ++j) p += (int)hist[tid * 16 + j];
        s_part[tid] = p;
    }
    __syncthreads();
    if (tid == 0) {
        int cum = 0, seg = 0;
        for (int t = 255; t >= 0; --t) {
            if (cum + s_part[t] >= KSEL) { seg = t; break; }
            cum += s_part[t];
        }
        int b = seg * 16;
        for (int j = 15; j >= 0; --j) {
            const int h = (int)hist[seg * 16 + j];
            if (cum + h >= KSEL) { b = seg * 16 + j; break; }
            cum += h;
        }
        s_binb = b;
        s_above = cum;       // count strictly above bin b
        s_nc = 0;
    }
    __syncthreads();
    const unsigned binb = (unsigned)s_binb;
    const int rneed = KSEL - s_above;   // rank of threshold within bin (>=1)

#pragma unroll
    for (int i = 0; i < 32; ++i) {
        if ((u[i] >> 19) == binb) {
            const int p = atomicAdd(&s_nc, 1);
            if (p < CANDCAP) s_cand[p] = u[i];
        }
    }
    __syncthreads();

    unsigned hi;
    if (s_nc <= CANDCAP) {
        const int nc = s_nc;
        const unsigned myv = (tid < nc) ? s_cand[tid] : 0u;
        unsigned t = binb << 19;
        for (int b = 18; b >= 0; --b) {
            const unsigned test = t | (1u << b);
            const int c = __syncthreads_count(tid < nc && myv >= test);
            if (c >= rneed) t = test;
        }
        hi = t;
    } else {
        unsigned t = 0;
        for (int b = 30; b >= 0; --b) {
            const unsigned test = t | (1u << b);
            int c = 0;
#pragma unroll
            for (int i = 0; i < 32; ++i) c += (u[i] >= test);
            c = __reduce_add_sync(0xFFFFFFFFu, c);
            if ((tid & 31) == 0) s_red[tid >> 5] = c;
            __syncthreads();
            if (tid == 0) {
                int tt = 0;
#pragma unroll
                for (int w = 0; w < 8; ++w) tt += s_red[w];
                s_total = tt;
            }
            __syncthreads();
            if (s_total >= KSEL) t = test;
        }
        hi = t;
    }

    // ----- classification + kc=504 Eigen arbitration (VALIDATED — unchanged) -----
    const float Tf  = __uint_as_float(hi);
    const float Thi = Tf + DELTA;
    const float Tlo = Tf - DELTA;

    __shared__ int s_nsure, s_nwin;
    __shared__ int   swin_idx[WINCAP];
    __shared__ float swin_val[WINCAP];
    if (tid == 0) { s_nsure = 0; s_nwin = 0; }
    __syncthreads();

    int*   idx_out = g_topk_idx + (size_t)row * KSEL;
    float* val_out = g_topk_val + (size_t)row * KSEL;

#pragma unroll
    for (int i = 0; i < 32; ++i) {
        const float va = __uint_as_float(u[i]);
        if (va >= Tlo) {
            const float fv = __uint_as_float(u[i] | (((smask >> i) & 1u) << 31));
            if (va > Thi) {
                const int p = atomicAdd(&s_nsure, 1);
                idx_out[p] = i * 256 + tid;
                val_out[p] = fv;
            } else {
                const int w = atomicAdd(&s_nwin, 1);
                if (w < WINCAP) { swin_idx[w] = i * 256 + tid; swin_val[w] = fv; }
            }
        }
    }
    __syncthreads();

    const int cHi  = s_nsure;
    int       cW   = s_nwin; if (cW > WINCAP) cW = WINCAP;
    const int need = KSEL - cHi;

    if (cW <= need) {
        if (tid < cW) {
            idx_out[cHi + tid] = swin_idx[tid];
            val_out[cHi + tid] = swin_val[tid];
        }
        return;
    }

    // slow path: emulate reference (Eigen gebp, kc=504) fp32 latent exactly
    __shared__ float s_emu[WINCAP];
    if (tid < cW) {
        const float* xr = x + (size_t)row * DIN;
        const float* wr = enc_w + (size_t)swin_idx[tid] * DIN;
        float s = 0.f;
        int k = 0;
#pragma unroll
        for (int blk = 0; blk < 3; ++blk) {
            const int kend = (blk < 2) ? (KC * (blk + 1)) : DIN;   // 504, 1008, 1024
            float p = 0.f;
            for (; k < kend; ++k) p = fmaf(xr[k], wr[k], p);
            s += p;
        }
        s_emu[tid] = fabsf(s + enc_b[swin_idx[tid]]);
    }
    __syncthreads();

    if (tid < cW) {
        const float mye = s_emu[tid];
        const int   myi = swin_idx[tid];
        int rank = 0;
        for (int c = 0; c < cW; ++c) {
            const float e = s_emu[c];
            if (e > mye || (e == mye && swin_idx[c] < myi)) rank++;
        }
        if (rank < need) {
            idx_out[cHi + rank] = myi;
            val_out[cHi + rank] = swin_val[tid];
        }
    }
}

// ---------------- kernel 5: sparse decoder ----------------
__global__ __launch_bounds__(256)
void decoder_kernel(float* __restrict__ mod) {
    const int row = blockIdx.x;
    const int tid = threadIdx.x;

    __shared__ int   sidx[KSEL];
    __shared__ float sval[KSEL];
    if (tid < KSEL) {
        sidx[tid] = g_topk_idx[(size_t)row * KSEL + tid];
        sval[tid] = g_topk_val[(size_t)row * KSEL + tid];
    }
    __syncthreads();

    float acc0 = 0.f, acc1 = 0.f, acc2 = 0.f, acc3 = 0.f;
#pragma unroll 4
    for (int j = 0; j < KSEL; ++j) {
        const float v = sval[j];
        const float* wrow = g_Wt + (size_t)sidx[j] * DIN;
        acc0 = fmaf(v, wrow[tid      ], acc0);
        acc1 = fmaf(v, wrow[tid + 256], acc1);
        acc2 = fmaf(v, wrow[tid + 512], acc2);
        acc3 = fmaf(v, wrow[tid + 768], acc3);
    }
    float* orow = mod + (size_t)row * DIN;
    orow[tid      ] = acc0;
    orow[tid + 256] = acc1;
    orow[tid + 512] = acc2;
    orow[tid + 768] = acc3;
}

// ---------------- launch ----------------
extern "C" void kernel_launch(void* const* d_in, const int* in_sizes, int n_in,
                              void* d_out, int out_size) {
    const float* x      = (const float*)d_in[0];
    const float* enc_w  = (const float*)d_in[1];
    const float* enc_b  = (const float*)d_in[2];
    const float* dec_w  = (const float*)d_in[3];
    const float* s      = (const float*)d_in[4];
    const float* prev_w = (const float*)d_in[5];
    const int*   task   = (const int*)d_in[6];

    float* out        = (float*)d_out;
    float* mod_out    = out;
    float* latent_out = out + (size_t)NROWS * DIN;
    float* W_out      = out + (size_t)NROWS * DIN + (size_t)NROWS * MLAT;

    __nv_bfloat16 *xh, *xl, *wh, *wl;
    cudaGetSymbolAddress((void**)&xh, g_x_hi);
    cudaGetSymbolAddress((void**)&xl, g_x_lo);
    cudaGetSymbolAddress((void**)&wh, g_w_hi);
    cudaGetSymbolAddress((void**)&wl, g_w_lo);

    cudaFuncSetAttribute(enc_gemm_mma, cudaFuncAttributeMaxDynamicSharedMemorySize, SMEM_GEMM);

    split_kernel<<<(NROWS * DIN / 4 + 255) / 256, 256>>>(x, xh, xl, NROWS * DIN / 4);
    split_kernel<<<(MLAT * DIN / 4 + 255) / 256, 256>>>(enc_w, wh, wl, MLAT * DIN / 4);
    compute_WT_kernel<<<dim3(MLAT / 32, DIN / 32), dim3(32, 8)>>>(dec_w, prev_w, s, task, W_out);
    enc_gemm_mma<<<dim3(MLAT / 128, NROWS / 128), 256, SMEM_GEMM>>>(latent_out, enc_b);
    topk_kernel<<<NROWS, 256>>>(latent_out, x, enc_w, enc_b);
    decoder_kernel<<<NROWS, 256>>>(mod_out);
}

// round 10
// speedup vs baseline: 1.1002x; 1.1002x over previous
#include <cuda_runtime.h>
#include <cuda_bf16.h>
#include <math.h>
#include <stdint.h>

#define NROWS 16384      // B*L
#define DIN   1024       // input dim
#define MLAT  8192       // latent dim
#define KSEL  64         // top-k
#define WINCAP 64        // max ambiguous candidates per row
#define DELTA 1e-4f      // ambiguity window (>> bf16-split GEMM noise ~5e-6)
#define KC    504        // Eigen gebp kc (VALIDATED round 5 — do not change)
#define CANDCAP 256      // in-bin candidate cap for fast threshold path

// ---------------- scratch (static __device__ — allocation-free) ----------------
__device__ float g_Wt[(size_t)MLAT * DIN];
__device__ __align__(16) __nv_bfloat16 g_x_hi[(size_t)NROWS * DIN];
__device__ __align__(16) __nv_bfloat16 g_x_lo[(size_t)NROWS * DIN];
__device__ __align__(16) __nv_bfloat16 g_w_hi[(size_t)MLAT * DIN];
__device__ __align__(16) __nv_bfloat16 g_w_lo[(size_t)MLAT * DIN];

// ---------------- PTX helpers (baseline ISA only — no 'a' features) ----------------
__device__ __forceinline__ uint32_t smem_u32(const void* p) {
    uint32_t a;
    asm("{ .reg .u64 t; cvta.to.shared.u64 t, %1; cvt.u32.u64 %0, t; }" : "=r"(a) : "l"(p));
    return a;
}
__device__ __forceinline__ void cp_async16(uint32_t s, const void* g) {
    asm volatile("cp.async.cg.shared.global [%0], [%1], 16;" :: "r"(s), "l"(g));
}
#define CP_COMMIT() asm volatile("cp.async.commit_group;" ::: "memory")
#define CP_WAIT(n)  asm volatile("cp.async.wait_group %0;" :: "n"(n) : "memory")

__device__ __forceinline__ void ldsm_x4(uint32_t* r, uint32_t addr) {
    asm volatile("ldmatrix.sync.aligned.m8n8.x4.shared.b16 {%0,%1,%2,%3}, [%4];"
        : "=r"(r[0]), "=r"(r[1]), "=r"(r[2]), "=r"(r[3]) : "r"(addr));
}
__device__ __forceinline__ void mma_bf16(float* d, const uint32_t* a, const uint32_t* b) {
    asm volatile("mma.sync.aligned.m16n8k16.row.col.f32.bf16.bf16.f32 "
        "{%0,%1,%2,%3}, {%4,%5,%6,%7}, {%8,%9}, {%0,%1,%2,%3};"
        : "+f"(d[0]), "+f"(d[1]), "+f"(d[2]), "+f"(d[3])
        : "r"(a[0]), "r"(a[1]), "r"(a[2]), "r"(a[3]), "r"(b[0]), "r"(b[1]));
}

// ---------------- kernel 0: fp32 -> bf16 hi/lo split ----------------
__global__ void split_kernel(const float* __restrict__ in,
                             __nv_bfloat16* __restrict__ hi,
                             __nv_bfloat16* __restrict__ lo, int n4) {
    const int i = blockIdx.x * blockDim.x + threadIdx.x;
    if (i >= n4) return;
    const float4 f = ((const float4*)in)[i];
    __nv_bfloat16 h0 = __float2bfloat16(f.x), h1 = __float2bfloat16(f.y);
    __nv_bfloat16 h2 = __float2bfloat16(f.z), h3 = __float2bfloat16(f.w);
    __nv_bfloat16 l0 = __float2bfloat16(f.x - __bfloat162float(h0));
    __nv_bfloat16 l1 = __float2bfloat16(f.y - __bfloat162float(h1));
    __nv_bfloat16 l2 = __float2bfloat16(f.z - __bfloat162float(h2));
    __nv_bfloat16 l3 = __float2bfloat16(f.w - __bfloat162float(h3));
    ushort4 H, L;
    H.x = __bfloat16_as_ushort(h0); H.y = __bfloat16_as_ushort(h1);
    H.z = __bfloat16_as_ushort(h2); H.w = __bfloat16_as_ushort(h3);
    L.x = __bfloat16_as_ushort(l0); L.y = __bfloat16_as_ushort(l1);
    L.z = __bfloat16_as_ushort(l2); L.w = __bfloat16_as_ushort(l3);
    ((ushort4*)hi)[i] = H;
    ((ushort4*)lo)[i] = L;
}

// ---------------- kernel 1+2 fused: W = prev + alpha*(dec-prev), write W and W^T ----------------
__global__ void compute_WT_kernel(const float* __restrict__ dec_w,
                                  const float* __restrict__ prev_w,
                                  const float* __restrict__ s_ptr,
                                  const int*   __restrict__ task_ptr,
                                  float* __restrict__ W_out) {
    __shared__ float tile[32][33];
    const int m0 = blockIdx.x * 32;   // latent dim
    const int d0 = blockIdx.y * 32;   // input dim
    const int tx = threadIdx.x, ty = threadIdx.y;
    const float s = *s_ptr;
    const int task = *task_ptr;
    const float sig = 1.0f / (1.0f + expf(-s));
    const float alpha = (task == 0) ? 1.0f : (1.0f / (float)(task + 1)) * sig;
#pragma unroll
    for (int j = 0; j < 32; j += 8) {
        const size_t idx = (size_t)(d0 + ty + j) * MLAT + m0 + tx;
        const float p = prev_w[idx];
        const float d = dec_w[idx];
        const float w = p + alpha * (d - p);   // match ref rounding: mul then add
        W_out[idx] = w;
        tile[ty + j][tx] = w;
    }
    __syncthreads();
#pragma unroll
    for (int j = 0; j < 32; j += 8)
        g_Wt[(size_t)(m0 + ty + j) * DIN + d0 + tx] = tile[tx][ty + j];
}

// ---------------- kernel 3: HMMA bf16-2split encoder GEMM (UNCHANGED r9/r7) ----------------
#define ROWB   80
#define TILE_B (128 * ROWB)
#define STAGE_BYTES (4 * TILE_B)
#define A_HI_OFF 0
#define A_LO_OFF TILE_B
#define B_HI_OFF (2 * TILE_B)
#define B_LO_OFF (3 * TILE_B)
#define SMEM_GEMM (2 * STAGE_BYTES)     // 81920 B

__global__ __launch_bounds__(256, 2)
void enc_gemm_mma(float* __restrict__ C, const float* __restrict__ bias) {
    extern __shared__ char smem[];
    const uint32_t sb = smem_u32(smem);
    const int tid = threadIdx.x;
    const int wid = tid >> 5, lid = tid & 31;
    const int m0 = blockIdx.y * 128, n0 = blockIdx.x * 128;
    const int warpM = wid >> 2, warpN = wid & 3;

    auto load_chunk = [&](int kt, int st) {
        const uint32_t base = sb + st * STAGE_BYTES;
#pragma unroll
        for (int t = 0; t < 2; ++t) {
            const int c = t * 256 + tid;          // 0..511
            const int row = c >> 2, q = c & 3;
            const size_t gA = (size_t)(m0 + row) * DIN + kt * 32 + q * 8;
            const size_t gB = (size_t)(n0 + row) * DIN + kt * 32 + q * 8;
            const uint32_t so = row * ROWB + q * 16;
            cp_async16(base + A_HI_OFF + so, g_x_hi + gA);
            cp_async16(base + A_LO_OFF + so, g_x_lo + gA);
            cp_async16(base + B_HI_OFF + so, g_w_hi + gB);
            cp_async16(base + B_LO_OFF + so, g_w_lo + gB);
        }
        CP_COMMIT();
    };

    float acc[4][4][4] = {};
    load_chunk(0, 0);

    for (int kt = 0; kt < 32; ++kt) {
        const int st = kt & 1;
        if (kt < 31) { load_chunk(kt + 1, st ^ 1); CP_WAIT(1); }
        else         { CP_WAIT(0); }
        __syncthreads();

        const uint32_t base = sb + st * STAGE_BYTES;
        const int arow = (lid & 8) + (lid & 7);
        const int brow = ((lid & 16) ? 8 : 0) + (lid & 7);
#pragma unroll
        for (int ks = 0; ks < 2; ++ks) {
            const int koff = ks * 32;
            const int akb = koff + ((lid & 16) ? 16 : 0);
            const int bkb = koff + ((lid & 8) ? 16 : 0);
            uint32_t Ah[4][4], Al[4][4], Bh[2][4], Bl[2][4];
#pragma unroll
            for (int mt = 0; mt < 4; ++mt) {
                const uint32_t r = (uint32_t)(warpM * 64 + mt * 16 + arow) * ROWB + akb;
                ldsm_x4(Ah[mt], base + A_HI_OFF + r);
                ldsm_x4(Al[mt], base + A_LO_OFF + r);
            }
#pragma unroll
            for (int ng = 0; ng < 2; ++ng) {
                const uint32_t r = (uint32_t)(warpN * 32 + ng * 16 + brow) * ROWB + bkb;
                ldsm_x4(Bh[ng], base + B_HI_OFF + r);
                ldsm_x4(Bl[ng], base + B_LO_OFF + r);
            }
#pragma unroll
            for (int mt = 0; mt < 4; ++mt)
#pragma unroll
                for (int ng = 0; ng < 2; ++ng)
#pragma unroll
                    for (int sub = 0; sub < 2; ++sub) {
                        float* d = acc[mt][ng * 2 + sub];
                        mma_bf16(d, Ah[mt], &Bh[ng][sub * 2]);
                        mma_bf16(d, Ah[mt], &Bl[ng][sub * 2]);
                        mma_bf16(d, Al[mt], &Bh[ng][sub * 2]);
                    }
        }
        __syncthreads();
    }

    const int rbase = m0 + warpM * 64 + (lid >> 2);
    const int cbase = n0 + warpN * 32 + (lid & 3) * 2;
#pragma unroll
    for (int nt = 0; nt < 4; ++nt) {
        const int col = cbase + nt * 8;
        const float b0 = bias[col], b1 = bias[col + 1];
#pragma unroll
        for (int mt = 0; mt < 4; ++mt) {
            float* p0 = C + (size_t)(rbase + mt * 16) * MLAT + col;
            float2 v0, v1;
            v0.x = acc[mt][nt][0] + b0; v0.y = acc[mt][nt][1] + b1;
            v1.x = acc[mt][nt][2] + b0; v1.y = acc[mt][nt][3] + b1;
            *(float2*)p0 = v0;
            *(float2*)(p0 + 8 * MLAT) = v1;
        }
    }
}

// ---------------- kernel 4: fused top-64 + decoder (vectorized loads) ----------------
// Per row: float4-read latent, histogram threshold, DELTA-window classification,
// kc=504 Eigen arbitration (VALIDATED semantics), then decode mod in the same block.
__global__ __launch_bounds__(256)
void topk_decode_kernel(const float* __restrict__ latent,
                        const float* __restrict__ x,
                        const float* __restrict__ enc_w,
                        const float* __restrict__ enc_b,
                        float* __restrict__ mod) {
    const int row = blockIdx.x;
    const int tid = threadIdx.x;
    const float* lrow = latent + (size_t)row * MLAT;

    __shared__ uint32_t hist[4096];     // 12-bit key = u >> 19
    __shared__ int s_part[256];
    __shared__ int s_binb, s_above, s_nc;
    __shared__ unsigned s_cand[CANDCAP];
    __shared__ int s_red[8];
    __shared__ int s_total;
    __shared__ int   s_sel_idx[KSEL];
    __shared__ float s_sel_val[KSEL];

#pragma unroll
    for (int i = 0; i < 16; ++i) hist[tid + i * 256] = 0;

    // vectorized read: 8x float4 per thread; value i -> column (i>>2)*1024 + tid*4 + (i&3)
    unsigned u[32];
    unsigned smask = 0;
#pragma unroll
    for (int j = 0; j < 8; ++j) {
        const float4 f = *(const float4*)(lrow + j * 1024 + tid * 4);
        const unsigned b0 = __float_as_uint(f.x), b1 = __float_as_uint(f.y);
        const unsigned b2 = __float_as_uint(f.z), b3 = __float_as_uint(f.w);
        u[j * 4 + 0] = b0 & 0x7FFFFFFFu;  smask |= (b0 >> 31) << (j * 4 + 0);
        u[j * 4 + 1] = b1 & 0x7FFFFFFFu;  smask |= (b1 >> 31) << (j * 4 + 1);
        u[j * 4 + 2] = b2 & 0x7FFFFFFFu;  smask |= (b2 >> 31) << (j * 4 + 2);
        u[j * 4 + 3] = b3 & 0x7FFFFFFFu;  smask |= (b3 >> 31) << (j * 4 + 3);
    }
    __syncthreads();
#pragma unroll
    for (int i = 0; i < 32; ++i) atomicAdd(&hist[u[i] >> 19], 1u);
    __syncthreads();

    // suffix scan to find bin of the 64th-largest
    {
        int p = 0;
#pragma unroll
        for (int j = 0; j < 16; ++j) p += (int)hist[tid * 16 + j];
        s_part[tid] = p;
    }
    __syncthreads();
    if (tid == 0) {
        int cum = 0, seg = 0;
        for (int t = 255; t >= 0; --t) {
            if (cum + s_part[t] >= KSEL) { seg = t; break; }
            cum += s_part[t];
        }
        int b = seg * 16;
        for (int j = 15; j >= 0; --j) {
            const int h = (int)hist[seg * 16 + j];
            if (cum + h >= KSEL) { b = seg * 16 + j; break; }
            cum += h;
        }
        s_binb = b;
        s_above = cum;
        s_nc = 0;
    }
    __syncthreads();
    const unsigned binb = (unsigned)s_binb;
    const int rneed = KSEL - s_above;

#pragma unroll
    for (int i = 0; i < 32; ++i) {
        if ((u[i] >> 19) == binb) {
            const int p = atomicAdd(&s_nc, 1);
            if (p < CANDCAP) s_cand[p] = u[i];
        }
    }
    __syncthreads();

    unsigned hi;
    if (s_nc <= CANDCAP) {
        const int nc = s_nc;
        const unsigned myv = (tid < nc) ? s_cand[tid] : 0u;
        unsigned t = binb << 19;
        for (int b = 18; b >= 0; --b) {
            const unsigned test = t | (1u << b);
            const int c = __syncthreads_count(tid < nc && myv >= test);
            if (c >= rneed) t = test;
        }
        hi = t;
    } else {
        unsigned t = 0;
        for (int b = 30; b >= 0; --b) {
            const unsigned test = t | (1u << b);
            int c = 0;
#pragma unroll
            for (int i = 0; i < 32; ++i) c += (u[i] >= test);
            c = __reduce_add_sync(0xFFFFFFFFu, c);
            if ((tid & 31) == 0) s_red[tid >> 5] = c;
            __syncthreads();
            if (tid == 0) {
                int tt = 0;
#pragma unroll
                for (int w = 0; w < 8; ++w) tt += s_red[w];
                s_total = tt;
            }
            __syncthreads();
            if (s_total >= KSEL) t = test;
        }
        hi = t;
    }

    // ----- classification + kc=504 Eigen arbitration (VALIDATED semantics) -----
    const float Tf  = __uint_as_float(hi);
    const float Thi = Tf + DELTA;
    const float Tlo = Tf - DELTA;

    __shared__ int s_nsure, s_nwin;
    __shared__ int   swin_idx[WINCAP];
    __shared__ float swin_val[WINCAP];
    if (tid == 0) { s_nsure = 0; s_nwin = 0; }
    __syncthreads();

#pragma unroll
    for (int i = 0; i < 32; ++i) {
        const float va = __uint_as_float(u[i]);
        if (va >= Tlo) {
            const int col = (i >> 2) * 1024 + tid * 4 + (i & 3);
            const float fv = __uint_as_float(u[i] | (((smask >> i) & 1u) << 31));
            if (va > Thi) {
                const int p = atomicAdd(&s_nsure, 1);
                s_sel_idx[p] = col;
                s_sel_val[p] = fv;
            } else {
                const int w = atomicAdd(&s_nwin, 1);
                if (w < WINCAP) { swin_idx[w] = col; swin_val[w] = fv; }
            }
        }
    }
    __syncthreads();

    const int cHi  = s_nsure;
    int       cW   = s_nwin; if (cW > WINCAP) cW = WINCAP;
    const int need = KSEL - cHi;

    if (cW <= need) {
        if (tid < cW) {
            s_sel_idx[cHi + tid] = swin_idx[tid];
            s_sel_val[cHi + tid] = swin_val[tid];
        }
    } else {
        // slow path: emulate reference (Eigen gebp, kc=504) fp32 latent exactly
        __shared__ float s_emu[WINCAP];
        if (tid < cW) {
            const float* xr = x + (size_t)row * DIN;
            const float* wr = enc_w + (size_t)swin_idx[tid] * DIN;
            float s = 0.f;
            int k = 0;
#pragma unroll
            for (int blk = 0; blk < 3; ++blk) {
                const int kend = (blk < 2) ? (KC * (blk + 1)) : DIN;   // 504, 1008, 1024
                float p = 0.f;
                for (; k < kend; ++k) p = fmaf(xr[k], wr[k], p);
                s += p;
            }
            s_emu[tid] = fabsf(s + enc_b[swin_idx[tid]]);
        }
        __syncthreads();
        if (tid < cW) {
            const float mye = s_emu[tid];
            const int   myi = swin_idx[tid];
            int rank = 0;
            for (int c = 0; c < cW; ++c) {
                const float e = s_emu[c];
                if (e > mye || (e == mye && swin_idx[c] < myi)) rank++;
            }
            if (rank < need) {
                s_sel_idx[cHi + rank] = myi;
                s_sel_val[cHi + rank] = swin_val[tid];
            }
        }
    }
    __syncthreads();

    // ----- fused decoder: mod[row, tid*4 .. tid*4+3] = sum_j val_j * Wt[idx_j, tid*4..] -----
    float4 acc = make_float4(0.f, 0.f, 0.f, 0.f);
    const int coff = tid * 4;
#pragma unroll 4
    for (int j = 0; j < KSEL; ++j) {
        const float v = s_sel_val[j];
        const float4 w = *(const float4*)(g_Wt + (size_t)s_sel_idx[j] * DIN + coff);
        acc.x = fmaf(v, w.x, acc.x);
        acc.y = fmaf(v, w.y, acc.y);
        acc.z = fmaf(v, w.z, acc.z);
        acc.w = fmaf(v, w.w, acc.w);
    }
    *(float4*)(mod + (size_t)row * DIN + coff) = acc;
}

// ---------------- launch ----------------
extern "C" void kernel_launch(void* const* d_in, const int* in_sizes, int n_in,
                              void* d_out, int out_size) {
    const float* x      = (const float*)d_in[0];
    const float* enc_w  = (const float*)d_in[1];
    const float* enc_b  = (const float*)d_in[2];
    const float* dec_w  = (const float*)d_in[3];
    const float* s      = (const float*)d_in[4];
    const float* prev_w = (const float*)d_in[5];
    const int*   task   = (const int*)d_in[6];

    float* out        = (float*)d_out;
    float* mod_out    = out;
    float* latent_out = out + (size_t)NROWS * DIN;
    float* W_out      = out + (size_t)NROWS * DIN + (size_t)NROWS * MLAT;

    __nv_bfloat16 *xh, *xl, *wh, *wl;
    cudaGetSymbolAddress((void**)&xh, g_x_hi);
    cudaGetSymbolAddress((void**)&xl, g_x_lo);
    cudaGetSymbolAddress((void**)&wh, g_w_hi);
    cudaGetSymbolAddress((void**)&wl, g_w_lo);

    cudaFuncSetAttribute(enc_gemm_mma, cudaFuncAttributeMaxDynamicSharedMemorySize, SMEM_GEMM);

    split_kernel<<<(NROWS * DIN / 4 + 255) / 256, 256>>>(x, xh, xl, NROWS * DIN / 4);
    split_kernel<<<(MLAT * DIN / 4 + 255) / 256, 256>>>(enc_w, wh, wl, MLAT * DIN / 4);
    compute_WT_kernel<<<dim3(MLAT / 32, DIN / 32), dim3(32, 8)>>>(dec_w, prev_w, s, task, W_out);
    enc_gemm_mma<<<dim3(MLAT / 128, NROWS / 128), 256, SMEM_GEMM>>>(latent_out, enc_b);
    topk_decode_kernel<<<NROWS, 256>>>(latent_out, x, enc_w, enc_b, mod_out);
}

// round 13
// speedup vs baseline: 1.1008x; 1.0005x over previous
#include <cuda_runtime.h>
#include <cuda_bf16.h>
#include <math.h>
#include <stdint.h>

#define NROWS 16384      // B*L
#define DIN   1024       // input dim
#define MLAT  8192       // latent dim
#define KSEL  64         // top-k
#define WINCAP 64        // max ambiguous candidates per row
#define DELTA 1e-4f      // ambiguity window (>> bf16-split GEMM noise ~5e-6)
#define KC    504        // Eigen gebp kc (VALIDATED round 5 — do not change)
#define CANDCAP 256      // in-bin candidate cap for fast threshold path

// ---------------- scratch (static __device__ — allocation-free) ----------------
__device__ float g_Wt[(size_t)MLAT * DIN];
__device__ __align__(16) __nv_bfloat16 g_x_hi[(size_t)NROWS * DIN];
__device__ __align__(16) __nv_bfloat16 g_x_lo[(size_t)NROWS * DIN];
__device__ __align__(16) __nv_bfloat16 g_w_hi[(size_t)MLAT * DIN];
__device__ __align__(16) __nv_bfloat16 g_w_lo[(size_t)MLAT * DIN];

// ---------------- PTX helpers (baseline ISA only — no 'a' features) ----------------
__device__ __forceinline__ uint32_t smem_u32(const void* p) {
    uint32_t a;
    asm("{ .reg .u64 t; cvta.to.shared.u64 t, %1; cvt.u32.u64 %0, t; }" : "=r"(a) : "l"(p));
    return a;
}
__device__ __forceinline__ void cp_async16(uint32_t s, const void* g) {
    asm volatile("cp.async.cg.shared.global [%0], [%1], 16;" :: "r"(s), "l"(g));
}
#define CP_COMMIT() asm volatile("cp.async.commit_group;" ::: "memory")
#define CP_WAIT(n)  asm volatile("cp.async.wait_group %0;" :: "n"(n) : "memory")

__device__ __forceinline__ void ldsm_x4(uint32_t* r, uint32_t addr) {
    asm volatile("ldmatrix.sync.aligned.m8n8.x4.shared.b16 {%0,%1,%2,%3}, [%4];"
        : "=r"(r[0]), "=r"(r[1]), "=r"(r[2]), "=r"(r[3]) : "r"(addr));
}
__device__ __forceinline__ void mma_bf16(float* d, const uint32_t* a, const uint32_t* b) {
    asm volatile("mma.sync.aligned.m16n8k16.row.col.f32.bf16.bf16.f32 "
        "{%0,%1,%2,%3}, {%4,%5,%6,%7}, {%8,%9}, {%0,%1,%2,%3};"
        : "+f"(d[0]), "+f"(d[1]), "+f"(d[2]), "+f"(d[3])
        : "r"(a[0]), "r"(a[1]), "r"(a[2]), "r"(a[3]), "r"(b[0]), "r"(b[1]));
}

// ---------------- kernel 0: fp32 -> bf16 hi/lo split ----------------
__global__ void split_kernel(const float* __restrict__ in,
                             __nv_bfloat16* __restrict__ hi,
                             __nv_bfloat16* __restrict__ lo, int n4) {
    const int i = blockIdx.x * blockDim.x + threadIdx.x;
    if (i >= n4) return;
    const float4 f = ((const float4*)in)[i];
    __nv_bfloat16 h0 = __float2bfloat16(f.x), h1 = __float2bfloat16(f.y);
    __nv_bfloat16 h2 = __float2bfloat16(f.z), h3 = __float2bfloat16(f.w);
    __nv_bfloat16 l0 = __float2bfloat16(f.x - __bfloat162float(h0));
    __nv_bfloat16 l1 = __float2bfloat16(f.y - __bfloat162float(h1));
    __nv_bfloat16 l2 = __float2bfloat16(f.z - __bfloat162float(h2));
    __nv_bfloat16 l3 = __float2bfloat16(f.w - __bfloat162float(h3));
    ushort4 H, L;
    H.x = __bfloat16_as_ushort(h0); H.y = __bfloat16_as_ushort(h1);
    H.z = __bfloat16_as_ushort(h2); H.w = __bfloat16_as_ushort(h3);
    L.x = __bfloat16_as_ushort(l0); L.y = __bfloat16_as_ushort(l1);
    L.z = __bfloat16_as_ushort(l2); L.w = __bfloat16_as_ushort(l3);
    ((ushort4*)hi)[i] = H;
    ((ushort4*)lo)[i] = L;
}

// ---------------- kernel 1+2 fused: W = prev + alpha*(dec-prev), write W and W^T ----------------
__global__ void compute_WT_kernel(const float* __restrict__ dec_w,
                                  const float* __restrict__ prev_w,
                                  const float* __restrict__ s_ptr,
                                  const int*   __restrict__ task_ptr,
                                  float* __restrict__ W_out) {
    __shared__ float tile[32][33];
    const int m0 = blockIdx.x * 32;   // latent dim
    const int d0 = blockIdx.y * 32;   // input dim
    const int tx = threadIdx.x, ty = threadIdx.y;
    const float s = *s_ptr;
    const int task = *task_ptr;
    const float sig = 1.0f / (1.0f + expf(-s));
    const float alpha = (task == 0) ? 1.0f : (1.0f / (float)(task + 1)) * sig;
#pragma unroll
    for (int j = 0; j < 32; j += 8) {
        const size_t idx = (size_t)(d0 + ty + j) * MLAT + m0 + tx;
        const float p = prev_w[idx];
        const float d = dec_w[idx];
        const float w = p + alpha * (d - p);   // match ref rounding: mul then add
        W_out[idx] = w;
        tile[ty + j][tx] = w;
    }
    __syncthreads();
#pragma unroll
    for (int j = 0; j < 32; j += 8)
        g_Wt[(size_t)(m0 + ty + j) * DIN + d0 + tx] = tile[tx][ty + j];
}

// ---------------- kernel 3: HMMA bf16-2split encoder GEMM (product-major mma order) ----------------
#define ROWB   80
#define TILE_B (128 * ROWB)
#define STAGE_BYTES (4 * TILE_B)
#define A_HI_OFF 0
#define A_LO_OFF TILE_B
#define B_HI_OFF (2 * TILE_B)
#define B_LO_OFF (3 * TILE_B)
#define SMEM_GEMM (2 * STAGE_BYTES)     // 81920 B

__global__ __launch_bounds__(256, 2)
void enc_gemm_mma(float* __restrict__ C, const float* __restrict__ bias) {
    extern __shared__ char smem[];
    const uint32_t sb = smem_u32(smem);
    const int tid = threadIdx.x;
    const int wid = tid >> 5, lid = tid & 31;
    const int m0 = blockIdx.y * 128, n0 = blockIdx.x * 128;
    const int warpM = wid >> 2, warpN = wid & 3;

    auto load_chunk = [&](int kt, int st) {
        const uint32_t base = sb + st * STAGE_BYTES;
#pragma unroll
        for (int t = 0; t < 2; ++t) {
            const int c = t * 256 + tid;          // 0..511
            const int row = c >> 2, q = c & 3;
            const size_t gA = (size_t)(m0 + row) * DIN + kt * 32 + q * 8;
            const size_t gB = (size_t)(n0 + row) * DIN + kt * 32 + q * 8;
            const uint32_t so = row * ROWB + q * 16;
            cp_async16(base + A_HI_OFF + so, g_x_hi + gA);
            cp_async16(base + A_LO_OFF + so, g_x_lo + gA);
            cp_async16(base + B_HI_OFF + so, g_w_hi + gB);
            cp_async16(base + B_LO_OFF + so, g_w_lo + gB);
        }
        CP_COMMIT();
    };

    float acc[4][4][4] = {};
    load_chunk(0, 0);

    for (int kt = 0; kt < 32; ++kt) {
        const int st = kt & 1;
        if (kt < 31) { load_chunk(kt + 1, st ^ 1); CP_WAIT(1); }
        else         { CP_WAIT(0); }
        __syncthreads();

        const uint32_t base = sb + st * STAGE_BYTES;
        const int arow = (lid & 8) + (lid & 7);
        const int brow = ((lid & 16) ? 8 : 0) + (lid & 7);
#pragma unroll
        for (int ks = 0; ks < 2; ++ks) {
            const int koff = ks * 32;
            const int akb = koff + ((lid & 16) ? 16 : 0);
            const int bkb = koff + ((lid & 8) ? 16 : 0);
            uint32_t Ah[4][4], Al[4][4], Bh[2][4], Bl[2][4];
#pragma unroll
            for (int mt = 0; mt < 4; ++mt) {
                const uint32_t r = (uint32_t)(warpM * 64 + mt * 16 + arow) * ROWB + akb;
                ldsm_x4(Ah[mt], base + A_HI_OFF + r);
                ldsm_x4(Al[mt], base + A_LO_OFF + r);
            }
#pragma unroll
            for (int ng = 0; ng < 2; ++ng) {
                const uint32_t r = (uint32_t)(warpN * 32 + ng * 16 + brow) * ROWB + bkb;
                ldsm_x4(Bh[ng], base + B_HI_OFF + r);
                ldsm_x4(Bl[ng], base + B_LO_OFF + r);
            }
            // product-major ordering: 16 independent mmas per pass, each accumulator
            // re-touched only after 16 intervening instructions (hides HMMA latency).
            // Per-accumulator product order stays hh -> hl -> lh: numerics BITWISE
            // identical to the (mt,ng,sub)-major ordering used in rounds 7-10.
#pragma unroll
            for (int mt = 0; mt < 4; ++mt)
#pragma unroll
                for (int ng = 0; ng < 2; ++ng)
#pragma unroll
                    for (int sub = 0; sub < 2; ++sub)
                        mma_bf16(acc[mt][ng * 2 + sub], Ah[mt], &Bh[ng][sub * 2]);
#pragma unroll
            for (int mt = 0; mt < 4; ++mt)
#pragma unroll
                for (int ng = 0; ng < 2; ++ng)
#pragma unroll
                    for (int sub = 0; sub < 2; ++sub)
                        mma_bf16(acc[mt][ng * 2 + sub], Ah[mt], &Bl[ng][sub * 2]);
#pragma unroll
            for (int mt = 0; mt < 4; ++mt)
#pragma unroll
                for (int ng = 0; ng < 2; ++ng)
#pragma unroll
                    for (int sub = 0; sub < 2; ++sub)
                        mma_bf16(acc[mt][ng * 2 + sub], Al[mt], &Bh[ng][sub * 2]);
        }
        __syncthreads();
    }

    const int rbase = m0 + warpM * 64 + (lid >> 2);
    const int cbase = n0 + warpN * 32 + (lid & 3) * 2;
#pragma unroll
    for (int nt = 0; nt < 4; ++nt) {
        const int col = cbase + nt * 8;
        const float b0 = bias[col], b1 = bias[col + 1];
#pragma unroll
        for (int mt = 0; mt < 4; ++mt) {
            float* p0 = C + (size_t)(rbase + mt * 16) * MLAT + col;
            float2 v0, v1;
            v0.x = acc[mt][nt][0] + b0; v0.y = acc[mt][nt][1] + b1;
            v1.x = acc[mt][nt][2] + b0; v1.y = acc[mt][nt][3] + b1;
            *(float2*)p0 = v0;
            *(float2*)(p0 + 8 * MLAT) = v1;
        }
    }
}

// ---------------- kernel 4: fused top-64 + decoder (vectorized loads) — UNCHANGED r10 ----------------
__global__ __launch_bounds__(256)
void topk_decode_kernel(const float* __restrict__ latent,
                        const float* __restrict__ x,
                        const float* __restrict__ enc_w,
                        const float* __restrict__ enc_b,
                        float* __restrict__ mod) {
    const int row = blockIdx.x;
    const int tid = threadIdx.x;
    const float* lrow = latent + (size_t)row * MLAT;

    __shared__ uint32_t hist[4096];     // 12-bit key = u >> 19
    __shared__ int s_part[256];
    __shared__ int s_binb, s_above, s_nc;
    __shared__ unsigned s_cand[CANDCAP];
    __shared__ int s_red[8];
    __shared__ int s_total;
    __shared__ int   s_sel_idx[KSEL];
    __shared__ float s_sel_val[KSEL];

#pragma unroll
    for (int i = 0; i < 16; ++i) hist[tid + i * 256] = 0;

    unsigned u[32];
    unsigned smask = 0;
#pragma unroll
    for (int j = 0; j < 8; ++j) {
        const float4 f = *(const float4*)(lrow + j * 1024 + tid * 4);
        const unsigned b0 = __float_as_uint(f.x), b1 = __float_as_uint(f.y);
        const unsigned b2 = __float_as_uint(f.z), b3 = __float_as_uint(f.w);
        u[j * 4 + 0] = b0 & 0x7FFFFFFFu;  smask |= (b0 >> 31) << (j * 4 + 0);
        u[j * 4 + 1] = b1 & 0x7FFFFFFFu;  smask |= (b1 >> 31) << (j * 4 + 1);
        u[j * 4 + 2] = b2 & 0x7FFFFFFFu;  smask |= (b2 >> 31) << (j * 4 + 2);
        u[j * 4 + 3] = b3 & 0x7FFFFFFFu;  smask |= (b3 >> 31) << (j * 4 + 3);
    }
    __syncthreads();
#pragma unroll
    for (int i = 0; i < 32; ++i) atomicAdd(&hist[u[i] >> 19], 1u);
    __syncthreads();

    {
        int p = 0;
#pragma unroll
        for (int j = 0; j < 16; ++j) p += (int)hist[tid * 16 + j];
        s_part[tid] = p;
    }
    __syncthreads();
    if (tid == 0) {
        int cum = 0, seg = 0;
        for (int t = 255; t >= 0; --t) {
            if (cum + s_part[t] >= KSEL) { seg = t; break; }
            cum += s_part[t];
        }
        int b = seg * 16;
        for (int j = 15; j >= 0; --j) {
            const int h = (int)hist[seg * 16 + j];
            if (cum + h >= KSEL) { b = seg * 16 + j; break; }
            cum += h;
        }
        s_binb = b;
        s_above = cum;
        s_nc = 0;
    }
    __syncthreads();
    const unsigned binb = (unsigned)s_binb;
    const int rneed = KSEL - s_above;

#pragma unroll
    for (int i = 0; i < 32; ++i) {
        if ((u[i] >> 19) == binb) {
            const int p = atomicAdd(&s_nc, 1);
            if (p < CANDCAP) s_cand[p] = u[i];
        }
    }
    __syncthreads();

    unsigned hi;
    if (s_nc <= CANDCAP) {
        const int nc = s_nc;
        const unsigned myv = (tid < nc) ? s_cand[tid] : 0u;
        unsigned t = binb << 19;
        for (int b = 18; b >= 0; --b) {
            const unsigned test = t | (1u << b);
            const int c = __syncthreads_count(tid < nc && myv >= test);
            if (c >= rneed) t = test;
        }
        hi = t;
    } else {
        unsigned t = 0;
        for (int b = 30; b >= 0; --b) {
            const unsigned test = t | (1u << b);
            int c = 0;
#pragma unroll
            for (int i = 0; i < 32; ++i) c += (u[i] >= test);
            c = __reduce_add_sync(0xFFFFFFFFu, c);
            if ((tid & 31) == 0) s_red[tid >> 5] = c;
            __syncthreads();
            if (tid == 0) {
                int tt = 0;
#pragma unroll
                for (int w = 0; w < 8; ++w) tt += s_red[w];
                s_total = tt;
            }
            __syncthreads();
            if (s_total >= KSEL) t = test;
        }
        hi = t;
    }

    const float Tf  = __uint_as_float(hi);
    const float Thi = Tf + DELTA;
    const float Tlo = Tf - DELTA;

    __shared__ int s_nsure, s_nwin;
    __shared__ int   swin_idx[WINCAP];
    __shared__ float swin_val[WINCAP];
    if (tid == 0) { s_nsure = 0; s_nwin = 0; }
    __syncthreads();

#pragma unroll
    for (int i = 0; i < 32; ++i) {
        const float va = __uint_as_float(u[i]);
        if (va >= Tlo) {
            const int col = (i >> 2) * 1024 + tid * 4 + (i & 3);
            const float fv = __uint_as_float(u[i] | (((smask >> i) & 1u) << 31));
            if (va > Thi) {
                const int p = atomicAdd(&s_nsure, 1);
                s_sel_idx[p] = col;
                s_sel_val[p] = fv;
            } else {
                const int w = atomicAdd(&s_nwin, 1);
                if (w < WINCAP) { swin_idx[w] = col; swin_val[w] = fv; }
            }
        }
    }
    __syncthreads();

    const int cHi  = s_nsure;
    int       cW   = s_nwin; if (cW > WINCAP) cW = WINCAP;
    const int need = KSEL - cHi;

    if (cW <= need) {
        if (tid < cW) {
            s_sel_idx[cHi + tid] = swin_idx[tid];
            s_sel_val[cHi + tid] = swin_val[tid];
        }
    } else {
        __shared__ float s_emu[WINCAP];
        if (tid < cW) {
            const float* xr = x + (size_t)row * DIN;
            const float* wr = enc_w + (size_t)swin_idx[tid] * DIN;
            float s = 0.f;
            int k = 0;
#pragma unroll
            for (int blk = 0; blk < 3; ++blk) {
                const int kend = (blk < 2) ? (KC * (blk + 1)) : DIN;   // 504, 1008, 1024
                float p = 0.f;
                for (; k < kend; ++k) p = fmaf(xr[k], wr[k], p);
                s += p;
            }
            s_emu[tid] = fabsf(s + enc_b[swin_idx[tid]]);
        }
        __syncthreads();
        if (tid < cW) {
            const float mye = s_emu[tid];
            const int   myi = swin_idx[tid];
            int rank = 0;
            for (int c = 0; c < cW; ++c) {
                const float e = s_emu[c];
                if (e > mye || (e == mye && swin_idx[c] < myi)) rank++;
            }
            if (rank < need) {
                s_sel_idx[cHi + rank] = myi;
                s_sel_val[cHi + rank] = swin_val[tid];
            }
        }
    }
    __syncthreads();

    float4 acc = make_float4(0.f, 0.f, 0.f, 0.f);
    const int coff = tid * 4;
#pragma unroll 4
    for (int j = 0; j < KSEL; ++j) {
        const float v = s_sel_val[j];
        const float4 w = *(const float4*)(g_Wt + (size_t)s_sel_idx[j] * DIN + coff);
        acc.x = fmaf(v, w.x, acc.x);
        acc.y = fmaf(v, w.y, acc.y);
        acc.z = fmaf(v, w.z, acc.z);
        acc.w = fmaf(v, w.w, acc.w);
    }
    *(float4*)(mod + (size_t)row * DIN + coff) = acc;
}

// ---------------- launch ----------------
extern "C" void kernel_launch(void* const* d_in, const int* in_sizes, int n_in,
                              void* d_out, int out_size) {
    const float* x      = (const float*)d_in[0];
    const float* enc_w  = (const float*)d_in[1];
    const float* enc_b  = (const float*)d_in[2];
    const float* dec_w  = (const float*)d_in[3];
    const float* s      = (const float*)d_in[4];
    const float* prev_w = (const float*)d_in[5];
    const int*   task   = (const int*)d_in[6];

    float* out        = (float*)d_out;
    float* mod_out    = out;
    float* latent_out = out + (size_t)NROWS * DIN;
    float* W_out      = out + (size_t)NROWS * DIN + (size_t)NROWS * MLAT;

    __nv_bfloat16 *xh, *xl, *wh, *wl;
    cudaGetSymbolAddress((void**)&xh, g_x_hi);
    cudaGetSymbolAddress((void**)&xl, g_x_lo);
    cudaGetSymbolAddress((void**)&wh, g_w_hi);
    cudaGetSymbolAddress((void**)&wl, g_w_lo);

    cudaFuncSetAttribute(enc_gemm_mma, cudaFuncAttributeMaxDynamicSharedMemorySize, SMEM_GEMM);

    split_kernel<<<(NROWS * DIN / 4 + 255) / 256, 256>>>(x, xh, xl, NROWS * DIN / 4);
    split_kernel<<<(MLAT * DIN / 4 + 255) / 256, 256>>>(enc_w, wh, wl, MLAT * DIN / 4);
    compute_WT_kernel<<<dim3(MLAT / 32, DIN / 32), dim3(32, 8)>>>(dec_w, prev_w, s, task, W_out);
    enc_gemm_mma<<<dim3(MLAT / 128, NROWS / 128), 256, SMEM_GEMM>>>(latent_out, enc_b);
    topk_decode_kernel<<<NROWS, 256>>>(latent_out, x, enc_w, enc_b, mod_out);
}